// round 2
// baseline (speedup 1.0000x reference)
#include <cuda_runtime.h>

// SimpleSelfAttention: out[b] = (gamma/sigma * (xf xf^T) W + I) @ xf[b]
// B=32, C=64, N=128*128=16384, fp32.
// Three kernels: Gram (xxT partials), M build (power iter + tiny matmul), Apply.

#define BATCH  32
#define CH     64
#define NPIX   16384
#define NP2    8192      // NPIX/2 (f32x2 units)
#define SPLITS 32
#define CHUNK  512       // NPIX / SPLITS
#define KSTEPS 16        // CHUNK/2/16

typedef unsigned long long u64;

// scratch: Gram partials (16 MB) and duplicated-f32x2 M^T (1 MB)
__device__ float g_part[BATCH * SPLITS * CH * CH];
__device__ u64   g_Mt[BATCH * CH * CH];

__device__ __forceinline__ u64 ffma2(u64 a, u64 b, u64 c) {
    u64 d;
    asm("fma.rn.f32x2 %0, %1, %2, %3;" : "=l"(d) : "l"(a), "l"(b), "l"(c));
    return d;
}

// ---------------------------------------------------------------------------
// Kernel A: Gram partials. grid = BATCH*SPLITS blocks, 128 threads.
// Each block: one batch b, 512 columns of n (256 pairs). Thread tile 8(c) x
// 4(d) over packed n-pairs (f32x2). smem tile [16 k-pairs][64 ch], row stride
// 66 to kill store conflicts; c-loads are warp-broadcast, d-loads stride-1.
// ---------------------------------------------------------------------------
__global__ __launch_bounds__(128) void gram_kernel(const float* __restrict__ x) {
    __shared__ u64 tile[16 * 66];
    const u64* xp = reinterpret_cast<const u64*>(x);
    const int b = blockIdx.x / SPLITS;
    const int s = blockIdx.x % SPLITS;
    const int t = threadIdx.x, tx = t & 15, ty = t >> 4;

    u64 acc[8][4];
#pragma unroll
    for (int i = 0; i < 8; i++)
#pragma unroll
        for (int j = 0; j < 4; j++) acc[i][j] = 0ULL;

    const long base = (long)b * CH * NP2 + s * (CHUNK / 2);

    for (int st = 0; st < KSTEPS; st++) {
        __syncthreads();
#pragma unroll
        for (int l = t; l < 1024; l += 128) {
            int c = l >> 4, k2 = l & 15;
            tile[k2 * 66 + c] = xp[base + (long)c * NP2 + st * 16 + k2];
        }
        __syncthreads();
#pragma unroll
        for (int k2 = 0; k2 < 16; k2++) {
            u64 va[8], vb[4];
#pragma unroll
            for (int i = 0; i < 8; i++) va[i] = tile[k2 * 66 + 8 * ty + i];
#pragma unroll
            for (int j = 0; j < 4; j++) vb[j] = tile[k2 * 66 + tx + 16 * j];
#pragma unroll
            for (int i = 0; i < 8; i++)
#pragma unroll
                for (int j = 0; j < 4; j++)
                    acc[i][j] = ffma2(va[i], vb[j], acc[i][j]);
        }
    }

    float* gp = g_part + (((long)b * SPLITS + s) << 12);
#pragma unroll
    for (int i = 0; i < 8; i++)
#pragma unroll
        for (int j = 0; j < 4; j++) {
            float2 v = *reinterpret_cast<float2*>(&acc[i][j]);
            gp[(8 * ty + i) * 64 + tx + 16 * j] = v.x + v.y;
        }
}

// ---------------------------------------------------------------------------
// Kernel B: reduce Gram partials, power-iteration sigma, build
// Mt[b][d][c] = (gamma/sigma) * sum_e xxT[c][e] W[e][d] + (c==d),
// stored duplicated into both f32x2 lanes. grid = BATCH, 256 threads.
// ---------------------------------------------------------------------------
__global__ void make_M_kernel(const float* __restrict__ Wg,
                              const float* __restrict__ gamma,
                              const float* __restrict__ ug) {
    __shared__ float sW[4096];
    __shared__ float sG[4096];
    __shared__ float sv[64], swv[64], su[64];
    __shared__ float s_inv, s_scale;

    const int b = blockIdx.x, t = threadIdx.x;

    for (int i = t; i < 4096; i += 256) sW[i] = Wg[i];
    if (t < 64) su[t] = ug[t];
    for (int i = t; i < 4096; i += 256) {
        float a = 0.f;
        const float* p = g_part + ((long)b * SPLITS << 12) + i;
#pragma unroll
        for (int s = 0; s < SPLITS; s++) a += p[s * 4096];
        sG[i] = a;
    }
    __syncthreads();

    // v = l2norm(W^T u)
    if (t < 64) {
        float a = 0.f;
        for (int r = 0; r < 64; r++) a += sW[r * 64 + t] * su[r];
        sv[t] = a;
    }
    __syncthreads();
    if (t == 0) {
        float n2 = 0.f;
        for (int c = 0; c < 64; c++) n2 += sv[c] * sv[c];
        s_inv = 1.f / fmaxf(sqrtf(n2), 1e-12f);
    }
    __syncthreads();
    // wv = W @ v_normalized
    if (t < 64) {
        float a = 0.f;
        for (int c = 0; c < 64; c++) a += sW[t * 64 + c] * (sv[c] * s_inv);
        swv[t] = a;
    }
    __syncthreads();
    if (t == 0) {
        float n2 = 0.f;
        for (int r = 0; r < 64; r++) n2 += swv[r] * swv[r];
        float nw = sqrtf(n2);
        float sigma = n2 / fmaxf(nw, 1e-12f);   // u2 @ (W v), exactly as reference
        s_scale = gamma[0] / sigma;
    }
    __syncthreads();

    for (int idx = t; idx < 4096; idx += 256) {
        int d = idx & 63, c = idx >> 6;         // lanes -> consecutive d (conflict-free)
        float a = 0.f;
        for (int e = 0; e < 64; e++) a += sG[c * 64 + e] * sW[e * 64 + d];
        float val = s_scale * a + ((c == d) ? 1.f : 0.f);
        unsigned int fb = __float_as_uint(val);
        g_Mt[((long)b << 12) + d * 64 + c] = ((u64)fb << 32) | fb;
    }
}

// ---------------------------------------------------------------------------
// Kernel C: out[b] = M[b] @ xf[b] (identity folded in). grid = BATCH*256
// blocks (64-col n-chunks), 128 threads. Thread tile 8(c) x 2(n-pairs).
// M rows broadcast from smem (pre-duplicated f32x2), x loads stride-1.
// smem: 32KB Mt + 16KB x tile = 48KB.
// ---------------------------------------------------------------------------
__global__ __launch_bounds__(128) void apply_kernel(const float* __restrict__ x,
                                                    float* __restrict__ out) {
    __shared__ u64 sMt[4096];
    __shared__ u64 sx[2048];
    const u64* xp = reinterpret_cast<const u64*>(x);
    u64* op = reinterpret_cast<u64*>(out);

    const int b = blockIdx.x >> 8;
    const int chunk = blockIdx.x & 255;
    const int t = threadIdx.x, tx = t & 15, ty = t >> 4;

#pragma unroll
    for (int i = t; i < 4096; i += 128) sMt[i] = g_Mt[((long)b << 12) + i];

    const long nb = (long)b * CH * NP2 + chunk * 32;
#pragma unroll
    for (int l = t; l < 2048; l += 128) {
        int d = l >> 5, k = l & 31;
        sx[d * 32 + k] = xp[nb + (long)d * NP2 + k];
    }
    __syncthreads();

    u64 acc[8][2];
#pragma unroll
    for (int i = 0; i < 8; i++) { acc[i][0] = 0ULL; acc[i][1] = 0ULL; }

#pragma unroll 8
    for (int d = 0; d < 64; d++) {
        u64 va[8], vb[2];
#pragma unroll
        for (int i = 0; i < 8; i++) va[i] = sMt[d * 64 + 8 * ty + i];
        vb[0] = sx[d * 32 + tx];
        vb[1] = sx[d * 32 + tx + 16];
#pragma unroll
        for (int i = 0; i < 8; i++) {
            acc[i][0] = ffma2(va[i], vb[0], acc[i][0]);
            acc[i][1] = ffma2(va[i], vb[1], acc[i][1]);
        }
    }

#pragma unroll
    for (int i = 0; i < 8; i++) {
        op[nb + (long)(8 * ty + i) * NP2 + tx]      = acc[i][0];
        op[nb + (long)(8 * ty + i) * NP2 + tx + 16] = acc[i][1];
    }
}

// ---------------------------------------------------------------------------
extern "C" void kernel_launch(void* const* d_in, const int* in_sizes, int n_in,
                              void* d_out, int out_size) {
    const float* x     = (const float*)d_in[0];
    const float* W     = (const float*)d_in[1];
    const float* gamma = (const float*)d_in[2];
    const float* u     = (const float*)d_in[3];
    float* out = (float*)d_out;

    gram_kernel<<<BATCH * SPLITS, 128>>>(x);
    make_M_kernel<<<BATCH, 256>>>(W, gamma, u);
    apply_kernel<<<BATCH * 256, 128>>>(x, out);
}